// round 13
// baseline (speedup 1.0000x reference)
#include <cuda_runtime.h>
#include <cuda_fp16.h>
#include <cstdint>

#define N_POINTS    2097152
#define CTA_THREADS 64
#define TILE_PTS    64                      // 2 warps x 32 rows
#define NTILES      (N_POINTS / TILE_PTS)   // 32768
#define NBLOCKS     (148 * 6)               // persistent

#define FSTR 20    // floats per feat row (16 data + 4 pad); row = 80B, 16B-aligned

static __device__ __forceinline__ uint32_t smem_u32(const void* p) {
    uint32_t a;
    asm("{ .reg .u64 t; cvta.to.shared.u64 t, %1; cvt.u32.u64 %0, t; }"
        : "=r"(a) : "l"(p));
    return a;
}
static __device__ __forceinline__ uint32_t pack_rn(float a, float b) {
    __half2 h = __floats2half2_rn(a, b);
    return *reinterpret_cast<uint32_t*>(&h);
}
static __device__ __forceinline__ __half2 u2h(uint32_t u) {
    return *reinterpret_cast<__half2*>(&u);
}
static __device__ __forceinline__ uint32_t h2u(__half2 h) {
    return *reinterpret_cast<uint32_t*>(&h);
}
static __device__ __forceinline__ float tanh_approx(float x) {
    float r; asm("tanh.approx.f32 %0, %1;" : "=f"(r) : "f"(x)); return r;
}

// m16n8k16 fp16 MMA, fp32 accumulate in place
static __device__ __forceinline__ void mma16(float* d, const uint32_t* a,
                                             uint32_t b0, uint32_t b1)
{
    asm volatile(
        "mma.sync.aligned.m16n8k16.row.col.f32.f16.f16.f32 "
        "{%0,%1,%2,%3}, {%4,%5,%6,%7}, {%8,%9}, {%0,%1,%2,%3};"
        : "+f"(d[0]), "+f"(d[1]), "+f"(d[2]), "+f"(d[3])
        : "r"(a[0]), "r"(a[1]), "r"(a[2]), "r"(a[3]), "r"(b0), "r"(b1));
}

// m16n8k16 fp16 MMA, fp16 D, C = 0
static __device__ __forceinline__ void mma16_h(uint32_t* d, const uint32_t* a,
                                               uint32_t b0, uint32_t b1)
{
    asm volatile(
        "mma.sync.aligned.m16n8k16.row.col.f16.f16.f16.f16 "
        "{%0,%1}, {%2,%3,%4,%5}, {%6,%7}, {%8,%8};"
        : "=r"(d[0]), "=r"(d[1])
        : "r"(a[0]), "r"(a[1]), "r"(a[2]), "r"(a[3]), "r"(b0), "r"(b1), "r"(0u));
}

// quad-cooperative gather issued as cp.async: 16B per lane, global -> SMEM,
// never touching the register file. Coords must be resident (prefetched).
static __device__ __forceinline__ void cell_gather_async(
    const float4* __restrict__ cellbase, uint32_t dst_base,
    float x, float y, float z, int g, int q)
{
    const int ix = (int)rintf(fminf(fmaxf(x * 127.0f, 0.0f), 127.0f));
    const int iy = (int)rintf(fminf(fmaxf(y * 127.0f, 0.0f), 127.0f));
    const int iz = (int)rintf(fminf(fmaxf(z * 127.0f, 0.0f), 127.0f));
    const uint32_t ci = (uint32_t)(((ix << 7) + iy) << 7) + (uint32_t)iz;
#pragma unroll
    for (int r = 0; r < 4; r++) {
        const int pp = r * 8 + g;
        const uint32_t cis = __shfl_sync(0xFFFFFFFFu, ci, pp);
        const float4* src = cellbase + (size_t)cis * 4 + q;
        const uint32_t dst = dst_base + (uint32_t)pp * (FSTR * 4) + (uint32_t)q * 16;
        asm volatile("cp.async.cg.shared.global [%0], [%1], 16;"
                     :: "r"(dst), "l"(src) : "memory");
    }
}

#define CPASYNC_COMMIT() asm volatile("cp.async.commit_group;" ::: "memory")
#define CPASYNC_WAIT1()  asm volatile("cp.async.wait_group 1;" ::: "memory")

__global__ void __launch_bounds__(CTA_THREADS, 6)
occ_mlp_kernel(const float* __restrict__ points, const float* __restrict__ grid,
               const float* __restrict__ W1, const float* __restrict__ b1,
               const float* __restrict__ W2, const float* __restrict__ b2,
               const float* __restrict__ W3, const float* __restrict__ b3,
               float* __restrict__ out)
{
    // fused epilogue table: j=nt*4+q -> (b2[c], b2[c+1], W3[c], W3[c+1]), c=2j
    __shared__ __align__(16) float4 sEp[32];
    __shared__ float sB3v;
    // double-buffered f32 feat scratch per warp: [warp][buf][32 rows x FSTR]
    __shared__ __align__(16) float sScr[2][2][32 * FSTR];  // 10 KB

    const int tid  = threadIdx.x;
    const int wid  = tid >> 5;
    const int lane = tid & 31;
    const int g    = lane >> 2;   // 0..7
    const int q    = lane & 3;    // 0..3

    // ---- W1 + W2 B-fragments + layer-1 bias register-resident ----
    uint2 w1f[8];
    uint32_t b1h[8];
#pragma unroll
    for (int nt = 0; nt < 8; nt++) {
        const float* Wn = W1 + (nt * 8 + g) * 16;
        w1f[nt].x = pack_rn(Wn[2 * q],     Wn[2 * q + 1]);
        w1f[nt].y = pack_rn(Wn[2 * q + 8], Wn[2 * q + 9]);
        const int c = nt * 8 + 2 * q;
        b1h[nt] = pack_rn(b1[c], b1[c + 1]);
    }
    uint2 w2f[4][8];   // 64 regs, loop-invariant
#pragma unroll
    for (int kt = 0; kt < 4; kt++)
#pragma unroll
        for (int nt = 0; nt < 8; nt++) {
            const float* Wn = W2 + (nt * 8 + g) * 64 + kt * 16 + 2 * q;
            w2f[kt][nt].x = pack_rn(Wn[0], Wn[1]);
            w2f[kt][nt].y = pack_rn(Wn[8], Wn[9]);
        }
    if (tid < 32) {
        const int c = 2 * tid;
        sEp[tid] = make_float4(b2[c], b2[c + 1], W3[c], W3[c + 1]);
    }
    if (tid == 0) sB3v = b3[0];
    __syncthreads();

    const float4* cellbase = (const float4*)grid;
    const __half2 zero2 = __floats2half2_rn(0.0f, 0.0f);
    const int lbase = wid * 32 + lane;

    uint32_t scrA[2];
    scrA[0] = smem_u32(&sScr[wid][0][0]);
    scrA[1] = smem_u32(&sScr[wid][1][0]);

    // ---- prologue: async-gather tile t0 into buf0; prefetch coords t1 ----
    float cx, cy, cz;
    {
        const int t0 = blockIdx.x;
        const int p = t0 * TILE_PTS + lbase;
        const float x0 = __ldg(points + 3 * p);
        const float y0 = __ldg(points + 3 * p + 1);
        const float z0 = __ldg(points + 3 * p + 2);
        cell_gather_async(cellbase, scrA[0], x0, y0, z0, g, q);
        CPASYNC_COMMIT();
        const int t1 = t0 + gridDim.x;
        if (t1 < NTILES) {
            const int pn = t1 * TILE_PTS + lbase;
            cx = __ldg(points + 3 * pn);
            cy = __ldg(points + 3 * pn + 1);
            cz = __ldg(points + 3 * pn + 2);
        }
    }

    int buf = 0;
    for (int tile = blockIdx.x; tile < NTILES; tile += gridDim.x) {
        const int p0 = tile * TILE_PTS + wid * 32;

        // ---- issue tile t+1 async gather into the other buffer ----
        const int ntile = tile + gridDim.x;
        if (ntile < NTILES)
            cell_gather_async(cellbase, scrA[buf ^ 1], cx, cy, cz, g, q);
        CPASYNC_COMMIT();   // always commit to keep depth bookkeeping

        // ---- issue coords loads for tile t+2 ----
        const int nntile = tile + 2 * gridDim.x;
        if (nntile < NTILES) {
            const int p = nntile * TILE_PTS + lbase;
            cx = __ldg(points + 3 * p);
            cy = __ldg(points + 3 * p + 1);
            cz = __ldg(points + 3 * p + 2);
        }

        // ---- wait for tile t's group, make writes warp-visible ----
        CPASYNC_WAIT1();
        __syncwarp();

        // ---- layer-1 A-fragments: f32 SMEM -> f16 packs ----
        const float* F = &sScr[wid][buf][0];
        uint32_t af[2][4];
#pragma unroll
        for (int rt = 0; rt < 2; rt++) {
            const int row = rt * 16 + g;
            const float2 v0 = *(const float2*)(F + row * FSTR + 2 * q);
            const float2 v1 = *(const float2*)(F + (row + 8) * FSTR + 2 * q);
            const float2 v2 = *(const float2*)(F + row * FSTR + 2 * q + 8);
            const float2 v3 = *(const float2*)(F + (row + 8) * FSTR + 2 * q + 8);
            af[rt][0] = pack_rn(v0.x, v0.y);
            af[rt][1] = pack_rn(v1.x, v1.y);
            af[rt][2] = pack_rn(v2.x, v2.y);
            af[rt][3] = pack_rn(v3.x, v3.y);
        }
        __syncwarp();   // reads done; buffer free for reuse next time around

        // ---- layer 1 (f16 D) -> layer-2 A-fragments ENTIRELY in registers ----
        uint32_t a2r[2][4][4];   // [rt][kt][areg]
#pragma unroll
        for (int nt = 0; nt < 8; nt++) {
            const int kt = nt >> 1, hi = (nt & 1) * 2;
#pragma unroll
            for (int rt = 0; rt < 2; rt++) {
                uint32_t d[2];
                mma16_h(d, af[rt], w1f[nt].x, w1f[nt].y);
                a2r[rt][kt][hi]     = h2u(__hmax2(__hadd2(u2h(d[0]), u2h(b1h[nt])), zero2));
                a2r[rt][kt][hi + 1] = h2u(__hmax2(__hadd2(u2h(d[1]), u2h(b1h[nt])), zero2));
            }
        }

        // ---- layer 2 + 3 fused: B operands straight from registers (no LDS) ----
        float s[4] = {0.0f, 0.0f, 0.0f, 0.0f};   // rows g, g+8, g+16, g+24
#pragma unroll
        for (int nt = 0; nt < 8; nt++) {
            float acc[2][4];
            acc[0][0] = acc[0][1] = acc[0][2] = acc[0][3] = 0.0f;
            acc[1][0] = acc[1][1] = acc[1][2] = acc[1][3] = 0.0f;
#pragma unroll
            for (int kt = 0; kt < 4; kt++) {
                mma16(acc[0], a2r[0][kt], w2f[kt][nt].x, w2f[kt][nt].y);
                mma16(acc[1], a2r[1][kt], w2f[kt][nt].x, w2f[kt][nt].y);
            }
            const float4 ep = sEp[nt * 4 + q];   // b2[c], b2[c+1], W3[c], W3[c+1]
            s[0] += fmaxf(acc[0][0] + ep.x, 0.0f) * ep.z
                  + fmaxf(acc[0][1] + ep.y, 0.0f) * ep.w;
            s[1] += fmaxf(acc[0][2] + ep.x, 0.0f) * ep.z
                  + fmaxf(acc[0][3] + ep.y, 0.0f) * ep.w;
            s[2] += fmaxf(acc[1][0] + ep.x, 0.0f) * ep.z
                  + fmaxf(acc[1][1] + ep.y, 0.0f) * ep.w;
            s[3] += fmaxf(acc[1][2] + ep.x, 0.0f) * ep.z
                  + fmaxf(acc[1][3] + ep.y, 0.0f) * ep.w;
        }
#pragma unroll
        for (int i = 0; i < 4; i++) {
            s[i] += __shfl_xor_sync(0xFFFFFFFFu, s[i], 1);
            s[i] += __shfl_xor_sync(0xFFFFFFFFu, s[i], 2);
        }
        if (q == 0) {
#pragma unroll
            for (int i = 0; i < 4; i++)
                out[p0 + g + i * 8] = tanh_approx(s[i] + sB3v);
        }

        buf ^= 1;
    }
}

// ---------------- Launch ----------------
extern "C" void kernel_launch(void* const* d_in, const int* in_sizes, int n_in,
                              void* d_out, int out_size)
{
    const float* points = (const float*)d_in[0];
    const float* grid   = (const float*)d_in[1];
    const float* W1     = (const float*)d_in[2];
    const float* b1     = (const float*)d_in[3];
    const float* W2     = (const float*)d_in[4];
    const float* b2     = (const float*)d_in[5];
    const float* W3     = (const float*)d_in[6];
    const float* b3     = (const float*)d_in[7];

    occ_mlp_kernel<<<NBLOCKS, CTA_THREADS>>>(points, grid, W1, b1, W2, b2, W3, b3,
                                             (float*)d_out);
}

// round 14
// speedup vs baseline: 1.0896x; 1.0896x over previous
#include <cuda_runtime.h>
#include <cuda_fp16.h>
#include <cstdint>

#define N_POINTS    2097152
#define CTA_THREADS 64
#define TILE_PTS    128                     // 2 warps x 64 rows
#define NTILES      (N_POINTS / TILE_PTS)   // 16384
#define NBLOCKS     (148 * 6)               // persistent

#define FSTR 20    // floats per feat row (16 data + 4 pad); row = 80B, 16B-aligned

static __device__ __forceinline__ uint32_t smem_u32(const void* p) {
    uint32_t a;
    asm("{ .reg .u64 t; cvta.to.shared.u64 t, %1; cvt.u32.u64 %0, t; }"
        : "=r"(a) : "l"(p));
    return a;
}
static __device__ __forceinline__ uint32_t pack_rn(float a, float b) {
    __half2 h = __floats2half2_rn(a, b);
    return *reinterpret_cast<uint32_t*>(&h);
}
static __device__ __forceinline__ __half2 u2h(uint32_t u) {
    return *reinterpret_cast<__half2*>(&u);
}
static __device__ __forceinline__ uint32_t h2u(__half2 h) {
    return *reinterpret_cast<uint32_t*>(&h);
}
static __device__ __forceinline__ float tanh_approx(float x) {
    float r; asm("tanh.approx.f32 %0, %1;" : "=f"(r) : "f"(x)); return r;
}

// m16n8k16 fp16 MMA, fp32 accumulate in place
static __device__ __forceinline__ void mma16(float* d, const uint32_t* a,
                                             uint32_t b0, uint32_t b1)
{
    asm volatile(
        "mma.sync.aligned.m16n8k16.row.col.f32.f16.f16.f32 "
        "{%0,%1,%2,%3}, {%4,%5,%6,%7}, {%8,%9}, {%0,%1,%2,%3};"
        : "+f"(d[0]), "+f"(d[1]), "+f"(d[2]), "+f"(d[3])
        : "r"(a[0]), "r"(a[1]), "r"(a[2]), "r"(a[3]), "r"(b0), "r"(b1));
}

// m16n8k16 fp16 MMA, fp16 D, C = 0
static __device__ __forceinline__ void mma16_h(uint32_t* d, const uint32_t* a,
                                               uint32_t b0, uint32_t b1)
{
    asm volatile(
        "mma.sync.aligned.m16n8k16.row.col.f16.f16.f16.f16 "
        "{%0,%1}, {%2,%3,%4,%5}, {%6,%7}, {%8,%8};"
        : "=r"(d[0]), "=r"(d[1])
        : "r"(a[0]), "r"(a[1]), "r"(a[2]), "r"(a[3]), "r"(b0), "r"(b1), "r"(0u));
}

// quad-cooperative async gather for 64 rows (2 points per lane).
static __device__ __forceinline__ void cell_gather_async64(
    const float4* __restrict__ cellbase, uint32_t dst_base,
    const float x[2], const float y[2], const float z[2], int g, int q)
{
    uint32_t ci[2];
#pragma unroll
    for (int h = 0; h < 2; h++) {
        const int ix = (int)rintf(fminf(fmaxf(x[h] * 127.0f, 0.0f), 127.0f));
        const int iy = (int)rintf(fminf(fmaxf(y[h] * 127.0f, 0.0f), 127.0f));
        const int iz = (int)rintf(fminf(fmaxf(z[h] * 127.0f, 0.0f), 127.0f));
        ci[h] = (uint32_t)(((ix << 7) + iy) << 7) + (uint32_t)iz;
    }
#pragma unroll
    for (int h = 0; h < 2; h++) {
#pragma unroll
        for (int r = 0; r < 4; r++) {
            const int pp = h * 32 + r * 8 + g;
            const uint32_t cis = __shfl_sync(0xFFFFFFFFu, ci[h], r * 8 + g);
            const float4* src = cellbase + (size_t)cis * 4 + q;
            const uint32_t dst = dst_base + (uint32_t)pp * (FSTR * 4) + (uint32_t)q * 16;
            asm volatile("cp.async.cg.shared.global [%0], [%1], 16;"
                         :: "r"(dst), "l"(src) : "memory");
        }
    }
}

#define CPASYNC_COMMIT() asm volatile("cp.async.commit_group;" ::: "memory")
#define CPASYNC_WAIT1()  asm volatile("cp.async.wait_group 1;" ::: "memory")

__global__ void __launch_bounds__(CTA_THREADS, 6)
occ_mlp_kernel(const float* __restrict__ points, const float* __restrict__ grid,
               const float* __restrict__ W1, const float* __restrict__ b1,
               const float* __restrict__ W2, const float* __restrict__ b2,
               const float* __restrict__ W3, const float* __restrict__ b3,
               float* __restrict__ out)
{
    // W2 B-fragments in SMEM: frag f=(kt*8+nt) -> [32 lanes] uint2  (R8 layout)
    __shared__ __align__(16) uint32_t sW2f[32 * 32 * 2];   // 8 KB
    // fused epilogue table: j=nt*4+q -> (b2[c], b2[c+1], W3[c], W3[c+1]), c=2j
    __shared__ __align__(16) float4 sEp[32];
    __shared__ float sB3v;
    // double-buffered f32 feat scratch per warp: [warp][buf][64 rows x FSTR]
    __shared__ __align__(16) float sScr[2][2][64 * FSTR];  // 20 KB

    const int tid  = threadIdx.x;
    const int wid  = tid >> 5;
    const int lane = tid & 31;
    const int g    = lane >> 2;   // 0..7
    const int q    = lane & 3;    // 0..3

    // ---- W1 B-fragments + layer-1 bias (half2) register-resident ----
    uint2 w1f[8];
    uint32_t b1h[8];
#pragma unroll
    for (int nt = 0; nt < 8; nt++) {
        const float* Wn = W1 + (nt * 8 + g) * 16;
        w1f[nt].x = pack_rn(Wn[2 * q],     Wn[2 * q + 1]);
        w1f[nt].y = pack_rn(Wn[2 * q + 8], Wn[2 * q + 9]);
        const int c = nt * 8 + 2 * q;
        b1h[nt] = pack_rn(b1[c], b1[c + 1]);
    }
    // ---- stage W2 fragments into SMEM ----
    for (int i = tid; i < 32 * 32 * 2; i += CTA_THREADS) {
        int f = i >> 6, ln = (i >> 1) & 31, r = i & 1;
        int kt = f >> 3, nt = f & 7;
        int n = nt * 8 + (ln >> 2);
        int k = kt * 16 + 2 * (ln & 3) + 8 * r;
        sW2f[i] = pack_rn(W2[n * 64 + k], W2[n * 64 + k + 1]);
    }
    if (tid < 32) {
        const int c = 2 * tid;
        sEp[tid] = make_float4(b2[c], b2[c + 1], W3[c], W3[c + 1]);
    }
    if (tid == 0) sB3v = b3[0];
    __syncthreads();

    const float4* cellbase = (const float4*)grid;
    const __half2 zero2 = __floats2half2_rn(0.0f, 0.0f);
    const int lbase = wid * 64 + lane;   // first of this lane's two coord points

    uint32_t scrA[2];
    scrA[0] = smem_u32(&sScr[wid][0][0]);
    scrA[1] = smem_u32(&sScr[wid][1][0]);

    // ---- prologue: async-gather tile t0 into buf0; prefetch coords t1 ----
    float cx[2], cy[2], cz[2];
    {
        const int t0 = blockIdx.x;
        float x0[2], y0[2], z0[2];
#pragma unroll
        for (int h = 0; h < 2; h++) {
            const int p = t0 * TILE_PTS + lbase + h * 32;
            x0[h] = __ldg(points + 3 * p);
            y0[h] = __ldg(points + 3 * p + 1);
            z0[h] = __ldg(points + 3 * p + 2);
        }
        cell_gather_async64(cellbase, scrA[0], x0, y0, z0, g, q);
        CPASYNC_COMMIT();
        const int t1 = t0 + gridDim.x;
        if (t1 < NTILES) {
#pragma unroll
            for (int h = 0; h < 2; h++) {
                const int p = t1 * TILE_PTS + lbase + h * 32;
                cx[h] = __ldg(points + 3 * p);
                cy[h] = __ldg(points + 3 * p + 1);
                cz[h] = __ldg(points + 3 * p + 2);
            }
        }
    }

    int buf = 0;
    for (int tile = blockIdx.x; tile < NTILES; tile += gridDim.x) {
        const int p0 = tile * TILE_PTS + wid * 64;

        // ---- issue tile t+1 async gather into the other buffer ----
        const int ntile = tile + gridDim.x;
        if (ntile < NTILES)
            cell_gather_async64(cellbase, scrA[buf ^ 1], cx, cy, cz, g, q);
        CPASYNC_COMMIT();

        // ---- issue coords loads for tile t+2 ----
        const int nntile = tile + 2 * gridDim.x;
        if (nntile < NTILES) {
#pragma unroll
            for (int h = 0; h < 2; h++) {
                const int p = nntile * TILE_PTS + lbase + h * 32;
                cx[h] = __ldg(points + 3 * p);
                cy[h] = __ldg(points + 3 * p + 1);
                cz[h] = __ldg(points + 3 * p + 2);
            }
        }

        // ---- wait for tile t's group ----
        CPASYNC_WAIT1();
        __syncwarp();

        // ---- layer-1 A-fragments (4 row-tiles): f32 SMEM -> f16 packs ----
        const float* F = &sScr[wid][buf][0];
        uint32_t af[4][4];
#pragma unroll
        for (int rt = 0; rt < 4; rt++) {
            const int row = rt * 16 + g;
            const float2 v0 = *(const float2*)(F + row * FSTR + 2 * q);
            const float2 v1 = *(const float2*)(F + (row + 8) * FSTR + 2 * q);
            const float2 v2 = *(const float2*)(F + row * FSTR + 2 * q + 8);
            const float2 v3 = *(const float2*)(F + (row + 8) * FSTR + 2 * q + 8);
            af[rt][0] = pack_rn(v0.x, v0.y);
            af[rt][1] = pack_rn(v1.x, v1.y);
            af[rt][2] = pack_rn(v2.x, v2.y);
            af[rt][3] = pack_rn(v3.x, v3.y);
        }
        __syncwarp();   // reads done; buffer free for reuse

        // ---- layer 1 (f16 D): 4 independent chains per nt ----
        uint32_t a2r[4][4][4];   // [rt][kt][areg] = 64 regs
#pragma unroll
        for (int nt = 0; nt < 8; nt++) {
            const int kt = nt >> 1, hi = (nt & 1) * 2;
#pragma unroll
            for (int rt = 0; rt < 4; rt++) {
                uint32_t d[2];
                mma16_h(d, af[rt], w1f[nt].x, w1f[nt].y);
                a2r[rt][kt][hi]     = h2u(__hmax2(__hadd2(u2h(d[0]), u2h(b1h[nt])), zero2));
                a2r[rt][kt][hi + 1] = h2u(__hmax2(__hadd2(u2h(d[1]), u2h(b1h[nt])), zero2));
            }
        }

        // ---- layer 2 + 3 fused: 4 independent acc chains per nt ----
        float s[8];
#pragma unroll
        for (int i = 0; i < 8; i++) s[i] = 0.0f;
#pragma unroll
        for (int nt = 0; nt < 8; nt++) {
            float acc[4][4];
#pragma unroll
            for (int rt = 0; rt < 4; rt++)
                acc[rt][0] = acc[rt][1] = acc[rt][2] = acc[rt][3] = 0.0f;
#pragma unroll
            for (int kt = 0; kt < 4; kt++) {
                const uint2 b = *(const uint2*)(sW2f + ((kt * 8 + nt) * 32 + lane) * 2);
#pragma unroll
                for (int rt = 0; rt < 4; rt++)
                    mma16(acc[rt], a2r[rt][kt], b.x, b.y);
            }
            const float4 ep = sEp[nt * 4 + q];   // b2[c], b2[c+1], W3[c], W3[c+1]
#pragma unroll
            for (int rt = 0; rt < 4; rt++) {
                s[2 * rt]     += fmaxf(acc[rt][0] + ep.x, 0.0f) * ep.z
                               + fmaxf(acc[rt][1] + ep.y, 0.0f) * ep.w;
                s[2 * rt + 1] += fmaxf(acc[rt][2] + ep.x, 0.0f) * ep.z
                               + fmaxf(acc[rt][3] + ep.y, 0.0f) * ep.w;
            }
        }
#pragma unroll
        for (int i = 0; i < 8; i++) {
            s[i] += __shfl_xor_sync(0xFFFFFFFFu, s[i], 1);
            s[i] += __shfl_xor_sync(0xFFFFFFFFu, s[i], 2);
        }
        if (q == 0) {
#pragma unroll
            for (int rt = 0; rt < 4; rt++) {
                out[p0 + rt * 16 + g]     = tanh_approx(s[2 * rt]     + sB3v);
                out[p0 + rt * 16 + 8 + g] = tanh_approx(s[2 * rt + 1] + sB3v);
            }
        }

        buf ^= 1;
    }
}

// ---------------- Launch ----------------
extern "C" void kernel_launch(void* const* d_in, const int* in_sizes, int n_in,
                              void* d_out, int out_size)
{
    const float* points = (const float*)d_in[0];
    const float* grid   = (const float*)d_in[1];
    const float* W1     = (const float*)d_in[2];
    const float* b1     = (const float*)d_in[3];
    const float* W2     = (const float*)d_in[4];
    const float* b2     = (const float*)d_in[5];
    const float* W3     = (const float*)d_in[6];
    const float* b3     = (const float*)d_in[7];

    occ_mlp_kernel<<<NBLOCKS, CTA_THREADS>>>(points, grid, W1, b1, W2, b2, W3, b3,
                                             (float*)d_out);
}